// round 15
// baseline (speedup 1.0000x reference)
#include <cuda_runtime.h>
#include <cuda_bf16.h>
#include <math.h>
#include <stdint.h>

#define N_NODES 50000
#define N_EDGES 800000

// ---------------- scratch (static device arrays; no cudaMalloc) -----------
__device__ float g_z[(size_t)N_NODES * 1024];   // pre-LN buffer
__device__ float g_h[(size_t)N_NODES * 1024];   // LN output
__device__ __nv_bfloat16 g_a1hi[(size_t)N_NODES * 1024];  // agg split
__device__ __nv_bfloat16 g_a1lo[(size_t)N_NODES * 1024];
__device__ __nv_bfloat16 g_a2hi[(size_t)N_NODES * 1024];  // residual-input split
__device__ __nv_bfloat16 g_a2lo[(size_t)N_NODES * 1024];
__device__ __nv_bfloat16 g_a3hi[(size_t)N_NODES * 1024];  // t split
__device__ __nv_bfloat16 g_a3lo[(size_t)N_NODES * 1024];
#define W_TOTAL 2752512
__device__ __nv_bfloat16 g_whi[W_TOTAL];
__device__ __nv_bfloat16 g_wlo[W_TOTAL];
// CSR scratch
__device__ int g_cnt[N_NODES];
__device__ int g_off[N_NODES];
__device__ int g_cur[N_NODES];
__device__ int g_esrc[N_EDGES];
__device__ int g_bsum[256];

// ============================ PTX helpers ==================================
__device__ __forceinline__ uint32_t smem_u32(const void* p) {
    uint32_t a;
    asm("{ .reg .u64 t; cvta.to.shared.u64 t, %1; cvt.u32.u64 %0, t; }" : "=r"(a) : "l"(p));
    return a;
}
__device__ __forceinline__ void cp16(uint32_t dst, const void* src, bool ok) {
    int sz = ok ? 16 : 0;
    asm volatile("cp.async.cg.shared.global [%0], [%1], 16, %2;" :: "r"(dst), "l"(src), "r"(sz) : "memory");
}
#define CP_COMMIT() asm volatile("cp.async.commit_group;" ::: "memory")

#define LDSM4(r0, r1, r2, r3, addr) \
    asm volatile("ldmatrix.sync.aligned.m8n8.x4.shared.b16 {%0,%1,%2,%3}, [%4];" \
                 : "=r"(r0), "=r"(r1), "=r"(r2), "=r"(r3) : "r"(addr))

#define MMA16816(d, a, b) \
    asm volatile("mma.sync.aligned.m16n8k16.row.col.f32.bf16.bf16.f32 " \
                 "{%0,%1,%2,%3}, {%4,%5,%6,%7}, {%8,%9}, {%0,%1,%2,%3};" \
                 : "+f"((d)[0]), "+f"((d)[1]), "+f"((d)[2]), "+f"((d)[3]) \
                 : "r"((a)[0]), "r"((a)[1]), "r"((a)[2]), "r"((a)[3]), "r"((b)[0]), "r"((b)[1]))

__device__ __forceinline__ __nv_bfloat162 split_hi2(float x, float y, __nv_bfloat162& lo) {
    __nv_bfloat16 hx = __float2bfloat16(x), hy = __float2bfloat16(y);
    lo = __nv_bfloat162(__float2bfloat16(x - __bfloat162float(hx)),
                        __float2bfloat16(y - __bfloat162float(hy)));
    return __nv_bfloat162(hx, hy);
}

// ======================= CSR build =========================================
__global__ void csr_zero(int* cnt, int* cur) {
    int i = blockIdx.x * 256 + threadIdx.x;
    if (i < N_NODES) { cnt[i] = 0; cur[i] = 0; }
}
__global__ void csr_hist(const int* __restrict__ ei, int* cnt) {
    int e = blockIdx.x * 256 + threadIdx.x;
    if (e < N_EDGES) atomicAdd(&cnt[ei[N_EDGES + e]], 1);
}
__global__ void csr_scan1(const int* __restrict__ cnt, int* off, int* bsum) {
    __shared__ int s[256];
    int i = blockIdx.x * 256 + threadIdx.x;
    int v = (i < N_NODES) ? cnt[i] : 0;
    s[threadIdx.x] = v;
    __syncthreads();
#pragma unroll
    for (int d = 1; d < 256; d <<= 1) {
        int t = (threadIdx.x >= d) ? s[threadIdx.x - d] : 0;
        __syncthreads();
        s[threadIdx.x] += t;
        __syncthreads();
    }
    if (i < N_NODES) off[i] = s[threadIdx.x] - v;
    if (threadIdx.x == 255) bsum[blockIdx.x] = s[255];
}
__global__ void csr_scan2(int* bsum, int nb) {
    __shared__ int s[256];
    int v = (threadIdx.x < nb) ? bsum[threadIdx.x] : 0;
    s[threadIdx.x] = v;
    __syncthreads();
#pragma unroll
    for (int d = 1; d < 256; d <<= 1) {
        int t = (threadIdx.x >= d) ? s[threadIdx.x - d] : 0;
        __syncthreads();
        s[threadIdx.x] += t;
        __syncthreads();
    }
    if (threadIdx.x < nb) bsum[threadIdx.x] = s[threadIdx.x] - v;
}
__global__ void csr_scan3(int* off, const int* __restrict__ bsum) {
    int i = blockIdx.x * 256 + threadIdx.x;
    if (i < N_NODES) off[i] += bsum[blockIdx.x];
}
__global__ void csr_fill(const int* __restrict__ ei, const int* __restrict__ off,
                         int* cur, int* esrc) {
    int e = blockIdx.x * 256 + threadIdx.x;
    if (e >= N_EDGES) return;
    int d = ei[N_EDGES + e];
    int p = off[d] + atomicAdd(&cur[d], 1);
    esrc[p] = ei[e];
}

// ================= aggregation: z = h[n] + sum_{src->n} h[src] =============
// 256-thread CTAs, 8-wide unrolled edge loop with dual accumulators.
template <int D>
__global__ void __launch_bounds__(256)
aggregate_kernel(const float* __restrict__ h, const int* __restrict__ off,
                 const int* __restrict__ cnt, const int* __restrict__ esrc,
                 __nv_bfloat162* __restrict__ hi, __nv_bfloat162* __restrict__ lo) {
    constexpr int TPN = D / 4;
    constexpr int NPB = 256 / TPN;
    const int node = blockIdx.x * NPB + threadIdx.x / TPN;
    if (node >= N_NODES) return;
    const int t = threadIdx.x % TPN;
    const float4* hp = (const float4*)h;

    float4 acc = hp[(size_t)node * TPN + t];
    float4 acc2 = make_float4(0.f, 0.f, 0.f, 0.f);
    const int s = off[node];
    const int e = s + cnt[node];
    int i = s;
#pragma unroll 1
    for (; i + 8 <= e; i += 8) {
        int s0 = esrc[i],     s1 = esrc[i + 1], s2 = esrc[i + 2], s3 = esrc[i + 3];
        int s4 = esrc[i + 4], s5 = esrc[i + 5], s6 = esrc[i + 6], s7 = esrc[i + 7];
        float4 v0 = hp[(size_t)s0 * TPN + t];
        float4 v1 = hp[(size_t)s1 * TPN + t];
        float4 v2 = hp[(size_t)s2 * TPN + t];
        float4 v3 = hp[(size_t)s3 * TPN + t];
        float4 v4 = hp[(size_t)s4 * TPN + t];
        float4 v5 = hp[(size_t)s5 * TPN + t];
        float4 v6 = hp[(size_t)s6 * TPN + t];
        float4 v7 = hp[(size_t)s7 * TPN + t];
        acc.x  += v0.x + v1.x + v2.x + v3.x;
        acc.y  += v0.y + v1.y + v2.y + v3.y;
        acc.z  += v0.z + v1.z + v2.z + v3.z;
        acc.w  += v0.w + v1.w + v2.w + v3.w;
        acc2.x += v4.x + v5.x + v6.x + v7.x;
        acc2.y += v4.y + v5.y + v6.y + v7.y;
        acc2.z += v4.z + v5.z + v6.z + v7.z;
        acc2.w += v4.w + v5.w + v6.w + v7.w;
    }
    for (; i + 4 <= e; i += 4) {
        int s0 = esrc[i], s1 = esrc[i + 1], s2 = esrc[i + 2], s3 = esrc[i + 3];
        float4 v0 = hp[(size_t)s0 * TPN + t];
        float4 v1 = hp[(size_t)s1 * TPN + t];
        float4 v2 = hp[(size_t)s2 * TPN + t];
        float4 v3 = hp[(size_t)s3 * TPN + t];
        acc.x += v0.x + v1.x + v2.x + v3.x;
        acc.y += v0.y + v1.y + v2.y + v3.y;
        acc.z += v0.z + v1.z + v2.z + v3.z;
        acc.w += v0.w + v1.w + v2.w + v3.w;
    }
    for (; i < e; i++) {
        float4 v = hp[(size_t)esrc[i] * TPN + t];
        acc.x += v.x; acc.y += v.y; acc.z += v.z; acc.w += v.w;
    }
    acc.x += acc2.x; acc.y += acc2.y; acc.z += acc2.z; acc.w += acc2.w;
    __nv_bfloat162 l0, l1;
    __nv_bfloat162 h0 = split_hi2(acc.x, acc.y, l0);
    __nv_bfloat162 h1 = split_hi2(acc.z, acc.w, l1);
    size_t o = (size_t)node * (D / 2) + t * 2;
    hi[o] = h0; hi[o + 1] = h1;
    lo[o] = l0; lo[o + 1] = l1;
}

// ---------------- batched prep: 9 weight splits + x activation split --------
struct WSplitJob { const float* w; __nv_bfloat16* hi; __nv_bfloat16* lo; int K, DO, tileBase; };
struct WSplitParams {
    WSplitJob jobs[9];
    int wTiles;                       // total weight tiles
    const float4* xa;                 // x activation split
    __nv_bfloat162* xhi; __nv_bfloat162* xlo;
    long xn4;
};

__global__ void prep_all_kernel(WSplitParams p) {
    const int b = blockIdx.x;
    if (b >= p.wTiles) {
        // activation split portion: 1024 threads per block, 1 float4 each
        long base = (long)(b - p.wTiles) * 1024 + (threadIdx.y * 32 + threadIdx.x);
        if (base < p.xn4) {
            float4 v = p.xa[base];
            __nv_bfloat162 l0, l1;
            __nv_bfloat162 h0 = split_hi2(v.x, v.y, l0);
            __nv_bfloat162 h1 = split_hi2(v.z, v.w, l1);
            p.xhi[2 * base] = h0; p.xhi[2 * base + 1] = h1;
            p.xlo[2 * base] = l0; p.xlo[2 * base + 1] = l1;
        }
        return;
    }
    int j = 0;
#pragma unroll
    for (int i = 1; i < 9; i++)
        if (b >= p.jobs[i].tileBase) j = i;
    const float* W = p.jobs[j].w;
    __nv_bfloat16* hi = p.jobs[j].hi;
    __nv_bfloat16* lo = p.jobs[j].lo;
    const int K = p.jobs[j].K, DO = p.jobs[j].DO;
    const int t = b - p.jobs[j].tileBase;
    const int tilesX = DO / 32;
    const int bx = t % tilesX, by = t / tilesX;

    __shared__ float s[32][33];
    int tx = threadIdx.x, ty = threadIdx.y;
    int k = by * 32 + ty, n = bx * 32 + tx;
    s[ty][tx] = W[(size_t)k * DO + n];
    __syncthreads();
    int on = bx * 32 + ty, ok = by * 32 + tx;
    float x = s[tx][ty];
    __nv_bfloat16 h = __float2bfloat16(x);
    __nv_bfloat16 l = __float2bfloat16(x - __bfloat162float(h));
    hi[(size_t)on * K + ok] = h;
    lo[(size_t)on * K + ok] = l;
}

// ---------------- split-bf16 HMMA GEMM pieces, BM=128 BN=256 BK=32 -----------
#define ROWB 80
#define A_PLANE (128 * ROWB)
#define B_PLANE (256 * ROWB)
#define STAGEB (2 * A_PLANE + 2 * B_PLANE)  // 61440
#define NSTAGE 3
#define GEMM_SMEM (NSTAGE * STAGEB)         // 184320
#define GEMM_THREADS 512

__device__ __forceinline__ void mma_loop(
    uint32_t sb, int bm, int bn,
    const __nv_bfloat16* __restrict__ Ahi, const __nv_bfloat16* __restrict__ Alo,
    const __nv_bfloat16* __restrict__ Bhi, const __nv_bfloat16* __restrict__ Blo,
    int N, int K, float (&acc)[2][8][4]) {
    const int tid = threadIdx.x;
    const int lane = tid & 31;
    const int wid = tid >> 5;
    const int wm = wid & 3;
    const int wn = wid >> 2;
    const int NC = K >> 5;

    auto load_stage = [&](int chunk, int s) {
        const uint32_t base = sb + s * STAGEB;
        const int k0 = chunk << 5;
        {
            int row = tid >> 2, c = tid & 3;
            uint32_t off = (uint32_t)row * ROWB + (uint32_t)c * 16u;
            long arow = bm + row;
            bool ok = arow < N;
            size_t ao = (size_t)(ok ? arow : 0) * K + k0 + c * 8;
            cp16(base + off,           Ahi + ao, ok);
            cp16(base + A_PLANE + off, Alo + ao, ok);
        }
#pragma unroll
        for (int j = 0; j < 2; j++) {
            int p = tid + j * GEMM_THREADS;
            int row = p >> 2, c = p & 3;
            uint32_t off = (uint32_t)row * ROWB + (uint32_t)c * 16u;
            size_t bo = (size_t)(bn + row) * K + k0 + c * 8;
            cp16(base + 2 * A_PLANE + off,           Bhi + bo, true);
            cp16(base + 2 * A_PLANE + B_PLANE + off, Blo + bo, true);
        }
    };

    load_stage(0, 0);
    CP_COMMIT();
    if (NC > 1) load_stage(1, 1);
    CP_COMMIT();

    const int a_row = wm * 32 + (lane & 15);
    const int a_cc  = (lane >> 4);
    const int b_row = wn * 64 + ((lane >> 4) << 3) + (lane & 7);
    const int b_cc  = ((lane >> 3) & 1);

    for (int i = 0; i < NC; i++) {
        asm volatile("cp.async.wait_group 1;" ::: "memory");
        __syncthreads();
        const int pf = i + 2;
        if (pf < NC) load_stage(pf, pf % NSTAGE);
        CP_COMMIT();

        const uint32_t sA  = sb + (i % NSTAGE) * STAGEB;
        const uint32_t sAl = sA + A_PLANE;
        const uint32_t sB  = sA + 2 * A_PLANE;
        const uint32_t sBl = sB + B_PLANE;

#pragma unroll
        for (int ks = 0; ks < 2; ks++) {
            uint32_t ah[2][4], al[2][4];
#pragma unroll
            for (int t = 0; t < 2; t++) {
                uint32_t off = (uint32_t)(a_row + t * 16) * ROWB + (uint32_t)(a_cc + ks * 2) * 16u;
                LDSM4(ah[t][0], ah[t][1], ah[t][2], ah[t][3], sA + off);
                LDSM4(al[t][0], al[t][1], al[t][2], al[t][3], sAl + off);
            }
#pragma unroll
            for (int g = 0; g < 4; g++) {
                uint32_t bh[2][2], bl[2][2];
                uint32_t off = (uint32_t)(b_row + g * 16) * ROWB + (uint32_t)(b_cc + ks * 2) * 16u;
                LDSM4(bh[0][0], bh[0][1], bh[1][0], bh[1][1], sB + off);
                LDSM4(bl[0][0], bl[0][1], bl[1][0], bl[1][1], sBl + off);
#pragma unroll
                for (int t = 0; t < 2; t++)
#pragma unroll
                    for (int s2 = 0; s2 < 2; s2++)
                        MMA16816(acc[t][2 * g + s2], ah[t], bh[s2]);
#pragma unroll
                for (int t = 0; t < 2; t++)
#pragma unroll
                    for (int s2 = 0; s2 < 2; s2++)
                        MMA16816(acc[t][2 * g + s2], ah[t], bl[s2]);
#pragma unroll
                for (int t = 0; t < 2; t++)
#pragma unroll
                    for (int s2 = 0; s2 < 2; s2++)
                        MMA16816(acc[t][2 * g + s2], al[t], bh[s2]);
            }
        }
    }
}

// t = relu(A@Wt + bias) -> split bf16 planes
__global__ void __launch_bounds__(GEMM_THREADS, 1)
gemm1_kernel(const __nv_bfloat16* __restrict__ Ahi, const __nv_bfloat16* __restrict__ Alo,
             const __nv_bfloat16* __restrict__ Bhi, const __nv_bfloat16* __restrict__ Blo,
             const float* __restrict__ bias,
             __nv_bfloat162* __restrict__ Chi, __nv_bfloat162* __restrict__ Clo,
             int N, int K, int DO) {
    extern __shared__ char smem[];
    const int bm = blockIdx.x * 128, bn = blockIdx.y * 256;
    const int lane = threadIdx.x & 31;
    const int wid = threadIdx.x >> 5;
    const int wm = wid & 3, wn = wid >> 2;

    float acc[2][8][4];
#pragma unroll
    for (int t = 0; t < 2; t++)
#pragma unroll
        for (int n = 0; n < 8; n++)
#pragma unroll
            for (int q = 0; q < 4; q++) acc[t][n][q] = 0.f;

    mma_loop(smem_u32(smem), bm, bn, Ahi, Alo, Bhi, Blo, N, K, acc);

#pragma unroll
    for (int t = 0; t < 2; t++) {
        const int rbase = bm + wm * 32 + t * 16 + (lane >> 2);
#pragma unroll
        for (int half = 0; half < 2; half++) {
            const long row = rbase + half * 8;
            if (row < N) {
#pragma unroll
                for (int n = 0; n < 8; n++) {
                    const int cb = bn + wn * 64 + n * 8 + (lane & 3) * 2;
                    float2 b2 = *(const float2*)(bias + cb);
                    float vx = fmaxf(acc[t][n][half * 2 + 0] + b2.x, 0.f);
                    float vy = fmaxf(acc[t][n][half * 2 + 1] + b2.y, 0.f);
                    __nv_bfloat162 lo2;
                    __nv_bfloat162 hi2 = split_hi2(vx, vy, lo2);
                    size_t o = ((size_t)row * DO + cb) >> 1;
                    Chi[o] = hi2;
                    Clo[o] = lo2;
                }
            }
        }
    }
}

// fused: z = relu( relu(T@Wb + bb) + Resin@Wr + rb )
__global__ void __launch_bounds__(GEMM_THREADS, 1)
gemm2f_kernel(const __nv_bfloat16* __restrict__ Thi, const __nv_bfloat16* __restrict__ Tlo,
              const __nv_bfloat16* __restrict__ Wbhi, const __nv_bfloat16* __restrict__ Wblo,
              const float* __restrict__ bb,
              const __nv_bfloat16* __restrict__ Rhi, const __nv_bfloat16* __restrict__ Rlo,
              const __nv_bfloat16* __restrict__ Wrhi, const __nv_bfloat16* __restrict__ Wrlo,
              const float* __restrict__ rb,
              float* __restrict__ C, int N, int K1, int K2, int DO) {
    extern __shared__ char smem[];
    const int bm = blockIdx.x * 128, bn = blockIdx.y * 256;
    const int lane = threadIdx.x & 31;
    const int wid = threadIdx.x >> 5;
    const int wm = wid & 3, wn = wid >> 2;
    const uint32_t sb = smem_u32(smem);

    float acc[2][8][4];
#pragma unroll
    for (int t = 0; t < 2; t++)
#pragma unroll
        for (int n = 0; n < 8; n++)
#pragma unroll
            for (int q = 0; q < 4; q++) acc[t][n][q] = 0.f;

    mma_loop(sb, bm, bn, Thi, Tlo, Wbhi, Wblo, N, K1, acc);

#pragma unroll
    for (int n = 0; n < 8; n++) {
        const int cb = bn + wn * 64 + n * 8 + (lane & 3) * 2;
        float2 b2 = *(const float2*)(bb + cb);
        float2 r2 = *(const float2*)(rb + cb);
#pragma unroll
        for (int t = 0; t < 2; t++) {
            acc[t][n][0] = fmaxf(acc[t][n][0] + b2.x, 0.f) + r2.x;
            acc[t][n][1] = fmaxf(acc[t][n][1] + b2.y, 0.f) + r2.y;
            acc[t][n][2] = fmaxf(acc[t][n][2] + b2.x, 0.f) + r2.x;
            acc[t][n][3] = fmaxf(acc[t][n][3] + b2.y, 0.f) + r2.y;
        }
    }

    asm volatile("cp.async.wait_group 0;" ::: "memory");
    __syncthreads();

    mma_loop(sb, bm, bn, Rhi, Rlo, Wrhi, Wrlo, N, K2, acc);

#pragma unroll
    for (int t = 0; t < 2; t++) {
        const int rbase = bm + wm * 32 + t * 16 + (lane >> 2);
#pragma unroll
        for (int half = 0; half < 2; half++) {
            const long row = rbase + half * 8;
            if (row < N) {
#pragma unroll
                for (int n = 0; n < 8; n++) {
                    const int cb = bn + wn * 64 + n * 8 + (lane & 3) * 2;
                    float2 o;
                    o.x = fmaxf(acc[t][n][half * 2 + 0], 0.f);
                    o.y = fmaxf(acc[t][n][half * 2 + 1], 0.f);
                    *(float2*)(C + row * DO + cb) = o;
                }
            }
        }
    }
}

// ---------------- row LayerNorm: blockDim.x == D/4 exactly -------------------
__global__ void ln_kernel(const float* __restrict__ in, const float* __restrict__ gam,
                          const float* __restrict__ bet, float* __restrict__ out,
                          __nv_bfloat162* __restrict__ ohi, __nv_bfloat162* __restrict__ olo,
                          int D) {
    const int row = blockIdx.x;
    const int i = threadIdx.x;
    const float4* ip = (const float4*)(in + (size_t)row * D);
    float4 x = ip[i];
    float s  = x.x + x.y + x.z + x.w;
    float ss = x.x * x.x + x.y * x.y + x.z * x.z + x.w * x.w;
#pragma unroll
    for (int o = 16; o; o >>= 1) {
        s  += __shfl_xor_sync(0xffffffffu, s, o);
        ss += __shfl_xor_sync(0xffffffffu, ss, o);
    }
    __shared__ float rs[8], rss[8], stats[2];
    const int w = i >> 5, l = i & 31;
    const int nw = blockDim.x >> 5;
    if (l == 0) { rs[w] = s; rss[w] = ss; }
    __syncthreads();
    if (i < 32) {
        float a = (i < nw) ? rs[i]  : 0.f;
        float b = (i < nw) ? rss[i] : 0.f;
#pragma unroll
        for (int o = 4; o; o >>= 1) {
            a += __shfl_xor_sync(0xffffffffu, a, o);
            b += __shfl_xor_sync(0xffffffffu, b, o);
        }
        if (i == 0) {
            float mu  = a / (float)D;
            float var = b / (float)D - mu * mu;
            stats[0] = mu;
            stats[1] = rsqrtf(var + 1e-5f);
        }
    }
    __syncthreads();
    const float mu = stats[0], inv = stats[1];
    float4 g = ((const float4*)gam)[i];
    float4 b = ((const float4*)bet)[i];
    float4 o;
    o.x = (x.x - mu) * inv * g.x + b.x;
    o.y = (x.y - mu) * inv * g.y + b.y;
    o.z = (x.z - mu) * inv * g.z + b.z;
    o.w = (x.w - mu) * inv * g.w + b.w;
    ((float4*)(out + (size_t)row * D))[i] = o;
    if (ohi) {
        __nv_bfloat162 l0, l1;
        __nv_bfloat162 h0 = split_hi2(o.x, o.y, l0);
        __nv_bfloat162 h1 = split_hi2(o.z, o.w, l1);
        size_t base = (size_t)row * (D >> 1) + i * 2;
        ohi[base] = h0; ohi[base + 1] = h1;
        olo[base] = l0; olo[base + 1] = l1;
    }
}

// ---------------- host orchestration ----------------------------------------
extern "C" void kernel_launch(void* const* d_in, const int* in_sizes, int n_in,
                              void* d_out, int out_size) {
    const float* x   = (const float*)d_in[0];
    const int*   ei  = (const int*)d_in[1];
    const float* w1a = (const float*)d_in[2];
    const float* b1a = (const float*)d_in[3];
    const float* w1b = (const float*)d_in[4];
    const float* b1b = (const float*)d_in[5];
    const float* w2a = (const float*)d_in[6];
    const float* b2a = (const float*)d_in[7];
    const float* w2b = (const float*)d_in[8];
    const float* b2b = (const float*)d_in[9];
    const float* w3a = (const float*)d_in[10];
    const float* b3a = (const float*)d_in[11];
    const float* w3b = (const float*)d_in[12];
    const float* b3b = (const float*)d_in[13];
    const float* rp1w = (const float*)d_in[14];
    const float* rp1b = (const float*)d_in[15];
    const float* rp2w = (const float*)d_in[16];
    const float* rp2b = (const float*)d_in[17];
    const float* rp3w = (const float*)d_in[18];
    const float* rp3b = (const float*)d_in[19];
    const float* ln1g = (const float*)d_in[20];
    const float* ln1b = (const float*)d_in[21];
    const float* ln2g = (const float*)d_in[22];
    const float* ln2b = (const float*)d_in[23];
    const float* ln3g = (const float*)d_in[24];
    const float* ln3b = (const float*)d_in[25];
    float* out = (float*)d_out;

    float *z, *h;
    __nv_bfloat16 *a1hi, *a1lo, *a2hi, *a2lo, *a3hi, *a3lo, *whi, *wlo;
    int *csr_cnt, *csr_off, *csr_cur, *esrc, *bsum;
    cudaGetSymbolAddress((void**)&z, g_z);
    cudaGetSymbolAddress((void**)&h, g_h);
    cudaGetSymbolAddress((void**)&a1hi, g_a1hi);
    cudaGetSymbolAddress((void**)&a1lo, g_a1lo);
    cudaGetSymbolAddress((void**)&a2hi, g_a2hi);
    cudaGetSymbolAddress((void**)&a2lo, g_a2lo);
    cudaGetSymbolAddress((void**)&a3hi, g_a3hi);
    cudaGetSymbolAddress((void**)&a3lo, g_a3lo);
    cudaGetSymbolAddress((void**)&whi, g_whi);
    cudaGetSymbolAddress((void**)&wlo, g_wlo);
    cudaGetSymbolAddress((void**)&csr_cnt, g_cnt);
    cudaGetSymbolAddress((void**)&csr_off, g_off);
    cudaGetSymbolAddress((void**)&csr_cur, g_cur);
    cudaGetSymbolAddress((void**)&esrc, g_esrc);
    cudaGetSymbolAddress((void**)&bsum, g_bsum);

    cudaFuncSetAttribute(gemm1_kernel, cudaFuncAttributeMaxDynamicSharedMemorySize, GEMM_SMEM);
    cudaFuncSetAttribute(gemm2f_kernel, cudaFuncAttributeMaxDynamicSharedMemorySize, GEMM_SMEM);

    // ---- CSR build (once per call) ----
    const int NB = (N_NODES + 255) / 256;
    const int EB = (N_EDGES + 255) / 256;
    csr_zero<<<NB, 256>>>(csr_cnt, csr_cur);
    csr_hist<<<EB, 256>>>(ei, csr_cnt);
    csr_scan1<<<NB, 256>>>(csr_cnt, csr_off, bsum);
    csr_scan2<<<1, 256>>>(bsum, NB);
    csr_scan3<<<NB, 256>>>(csr_off, bsum);
    csr_fill<<<EB, 256>>>(ei, csr_off, csr_cur, esrc);

    // ---- prep: 9 weight splits + x activation split, one launch ----
    const size_t o_w1a = 0;
    const size_t o_w1b = o_w1a + 128 * 256;
    const size_t o_rp1 = o_w1b + 256 * 256;
    const size_t o_w2a = o_rp1 + 128 * 256;
    const size_t o_w2b = o_w2a + 256 * 512;
    const size_t o_rp2 = o_w2b + 512 * 512;
    const size_t o_w3a = o_rp2 + 256 * 512;
    const size_t o_w3b = o_w3a + 512 * 1024;
    const size_t o_rp3 = o_w3b + 1024 * 1024;

    {
        struct Src { const float* w; size_t off; int K, DO; };
        const Src srcs[9] = {
            {w1a, o_w1a, 128, 256},  {w1b, o_w1b, 256, 256},   {rp1w, o_rp1, 128, 256},
            {w2a, o_w2a, 256, 512},  {w2b, o_w2b, 512, 512},   {rp2w, o_rp2, 256, 512},
            {w3a, o_w3a, 512, 1024}, {w3b, o_w3b, 1024, 1024}, {rp3w, o_rp3, 512, 1024},
        };
        WSplitParams p;
        int tiles = 0;
        for (int i = 0; i < 9; i++) {
            p.jobs[i].w = srcs[i].w;
            p.jobs[i].hi = whi + srcs[i].off;
            p.jobs[i].lo = wlo + srcs[i].off;
            p.jobs[i].K = srcs[i].K;
            p.jobs[i].DO = srcs[i].DO;
            p.jobs[i].tileBase = tiles;
            tiles += (srcs[i].DO / 32) * (srcs[i].K / 32);
        }
        p.wTiles = tiles;
        p.xa = (const float4*)x;
        p.xhi = (__nv_bfloat162*)a2hi;
        p.xlo = (__nv_bfloat162*)a2lo;
        p.xn4 = (long)N_NODES * 128 / 4;
        int xblocks = (int)((p.xn4 + 1023) / 1024);
        dim3 b(32, 32);
        prep_all_kernel<<<tiles + xblocks, b>>>(p);
    }

    const __nv_bfloat16* rw_hi[3] = {whi + o_rp1, whi + o_rp2, whi + o_rp3};
    const __nv_bfloat16* rw_lo[3] = {wlo + o_rp1, wlo + o_rp2, wlo + o_rp3};
    const float* rb[3] = {rp1b, rp2b, rp3b};
    const __nv_bfloat16* wa_hi[3] = {whi + o_w1a, whi + o_w2a, whi + o_w3a};
    const __nv_bfloat16* wa_lo[3] = {wlo + o_w1a, wlo + o_w2a, wlo + o_w3a};
    const float* ba[3] = {b1a, b2a, b3a};
    const __nv_bfloat16* wb_hi[3] = {whi + o_w1b, whi + o_w2b, whi + o_w3b};
    const __nv_bfloat16* wb_lo[3] = {wlo + o_w1b, wlo + o_w2b, wlo + o_w3b};
    const float* bb[3] = {b1b, b2b, b3b};
    const float* lg[3] = {ln1g, ln2g, ln3g};
    const float* lb[3] = {ln1b, ln2b, ln3b};
    const int din[3]  = {128, 256, 512};
    const int dout[3] = {256, 512, 1024};
    const float* blockIn[3] = {x, h, h};

    const int gx = (N_NODES + 127) / 128;

    for (int blk = 0; blk < 3; blk++) {
        const int d = din[blk], dO = dout[blk];

        // aggregation (memory-bound, high occupancy, 256-thread CTAs)
        if (blk == 0) {
            const int npb = 256 / (128 / 4);
            aggregate_kernel<128><<<(N_NODES + npb - 1) / npb, 256>>>(
                blockIn[blk], csr_off, csr_cnt, esrc,
                (__nv_bfloat162*)a1hi, (__nv_bfloat162*)a1lo);
        } else if (blk == 1) {
            const int npb = 256 / (256 / 4);
            aggregate_kernel<256><<<(N_NODES + npb - 1) / npb, 256>>>(
                blockIn[blk], csr_off, csr_cnt, esrc,
                (__nv_bfloat162*)a1hi, (__nv_bfloat162*)a1lo);
        } else {
            const int npb = 256 / (512 / 4);
            aggregate_kernel<512><<<(N_NODES + npb - 1) / npb, 256>>>(
                blockIn[blk], csr_off, csr_cnt, esrc,
                (__nv_bfloat162*)a1hi, (__nv_bfloat162*)a1lo);
        }

        // t = relu(agg@Wa+ba) -> split planes a3
        {
            dim3 grid(gx, dO / 256);
            gemm1_kernel<<<grid, GEMM_THREADS, GEMM_SMEM>>>(
                a1hi, a1lo, wa_hi[blk], wa_lo[blk], ba[blk],
                (__nv_bfloat162*)a3hi, (__nv_bfloat162*)a3lo, N_NODES, d, dO);
        }

        // z = relu( relu(t@Wb+bb) + resin@Wr + rb )   (fused residual GEMM)
        {
            dim3 grid(gx, dO / 256);
            gemm2f_kernel<<<grid, GEMM_THREADS, GEMM_SMEM>>>(
                a3hi, a3lo, wb_hi[blk], wb_lo[blk], bb[blk],
                a2hi, a2lo, rw_hi[blk], rw_lo[blk], rb[blk],
                z, N_NODES, dO, d, dO);
        }

        // LN (writes next block's residual-input split planes, except last)
        if (blk < 2)
            ln_kernel<<<N_NODES, dO / 4>>>(z, lg[blk], lb[blk], h,
                                           (__nv_bfloat162*)a2hi, (__nv_bfloat162*)a2lo, dO);
        else
            ln_kernel<<<N_NODES, dO / 4>>>(z, lg[blk], lb[blk], out, nullptr, nullptr, dO);
    }
}

// round 16
// speedup vs baseline: 1.0237x; 1.0237x over previous
#include <cuda_runtime.h>
#include <cuda_bf16.h>
#include <math.h>
#include <stdint.h>

#define N_NODES 50000
#define N_EDGES 800000

// ---------------- scratch (static device arrays; no cudaMalloc) -----------
__device__ float g_z[(size_t)N_NODES * 1024];   // pre-LN buffer
__device__ float g_h[(size_t)N_NODES * 1024];   // LN output
__device__ __nv_bfloat16 g_a1hi[(size_t)N_NODES * 1024];  // agg split
__device__ __nv_bfloat16 g_a1lo[(size_t)N_NODES * 1024];
__device__ __nv_bfloat16 g_a2hi[(size_t)N_NODES * 1024];  // residual-input split
__device__ __nv_bfloat16 g_a2lo[(size_t)N_NODES * 1024];
__device__ __nv_bfloat16 g_a3hi[(size_t)N_NODES * 1024];  // t split
__device__ __nv_bfloat16 g_a3lo[(size_t)N_NODES * 1024];
#define W_TOTAL 2752512
__device__ __nv_bfloat16 g_whi[W_TOTAL];
__device__ __nv_bfloat16 g_wlo[W_TOTAL];
// CSR scratch
__device__ int g_cnt[N_NODES];
__device__ int g_off[N_NODES];
__device__ int g_cur[N_NODES];
__device__ int g_esrc[N_EDGES];
__device__ int g_bsum[256];

// ============================ PTX helpers ==================================
__device__ __forceinline__ uint32_t smem_u32(const void* p) {
    uint32_t a;
    asm("{ .reg .u64 t; cvta.to.shared.u64 t, %1; cvt.u32.u64 %0, t; }" : "=r"(a) : "l"(p));
    return a;
}
__device__ __forceinline__ void cp16(uint32_t dst, const void* src, bool ok) {
    int sz = ok ? 16 : 0;
    asm volatile("cp.async.cg.shared.global [%0], [%1], 16, %2;" :: "r"(dst), "l"(src), "r"(sz) : "memory");
}
#define CP_COMMIT() asm volatile("cp.async.commit_group;" ::: "memory")

#define LDSM4(r0, r1, r2, r3, addr) \
    asm volatile("ldmatrix.sync.aligned.m8n8.x4.shared.b16 {%0,%1,%2,%3}, [%4];" \
                 : "=r"(r0), "=r"(r1), "=r"(r2), "=r"(r3) : "r"(addr))

#define MMA16816(d, a, b) \
    asm volatile("mma.sync.aligned.m16n8k16.row.col.f32.bf16.bf16.f32 " \
                 "{%0,%1,%2,%3}, {%4,%5,%6,%7}, {%8,%9}, {%0,%1,%2,%3};" \
                 : "+f"((d)[0]), "+f"((d)[1]), "+f"((d)[2]), "+f"((d)[3]) \
                 : "r"((a)[0]), "r"((a)[1]), "r"((a)[2]), "r"((a)[3]), "r"((b)[0]), "r"((b)[1]))

__device__ __forceinline__ __nv_bfloat162 split_hi2(float x, float y, __nv_bfloat162& lo) {
    __nv_bfloat16 hx = __float2bfloat16(x), hy = __float2bfloat16(y);
    lo = __nv_bfloat162(__float2bfloat16(x - __bfloat162float(hx)),
                        __float2bfloat16(y - __bfloat162float(hy)));
    return __nv_bfloat162(hx, hy);
}

// ======================= CSR build =========================================
__global__ void csr_zero(int* cnt, int* cur) {
    int i = blockIdx.x * 256 + threadIdx.x;
    if (i < N_NODES) { cnt[i] = 0; cur[i] = 0; }
}
__global__ void csr_hist(const int* __restrict__ ei, int* cnt) {
    int e = blockIdx.x * 256 + threadIdx.x;
    if (e < N_EDGES) atomicAdd(&cnt[ei[N_EDGES + e]], 1);
}
__global__ void csr_scan1(const int* __restrict__ cnt, int* off, int* bsum) {
    __shared__ int s[256];
    int i = blockIdx.x * 256 + threadIdx.x;
    int v = (i < N_NODES) ? cnt[i] : 0;
    s[threadIdx.x] = v;
    __syncthreads();
#pragma unroll
    for (int d = 1; d < 256; d <<= 1) {
        int t = (threadIdx.x >= d) ? s[threadIdx.x - d] : 0;
        __syncthreads();
        s[threadIdx.x] += t;
        __syncthreads();
    }
    if (i < N_NODES) off[i] = s[threadIdx.x] - v;
    if (threadIdx.x == 255) bsum[blockIdx.x] = s[255];
}
__global__ void csr_scan2(int* bsum, int nb) {
    __shared__ int s[256];
    int v = (threadIdx.x < nb) ? bsum[threadIdx.x] : 0;
    s[threadIdx.x] = v;
    __syncthreads();
#pragma unroll
    for (int d = 1; d < 256; d <<= 1) {
        int t = (threadIdx.x >= d) ? s[threadIdx.x - d] : 0;
        __syncthreads();
        s[threadIdx.x] += t;
        __syncthreads();
    }
    if (threadIdx.x < nb) bsum[threadIdx.x] = s[threadIdx.x] - v;
}
__global__ void csr_scan3(int* off, const int* __restrict__ bsum) {
    int i = blockIdx.x * 256 + threadIdx.x;
    if (i < N_NODES) off[i] += bsum[blockIdx.x];
}
__global__ void csr_fill(const int* __restrict__ ei, const int* __restrict__ off,
                         int* cur, int* esrc) {
    int e = blockIdx.x * 256 + threadIdx.x;
    if (e >= N_EDGES) return;
    int d = ei[N_EDGES + e];
    int p = off[d] + atomicAdd(&cur[d], 1);
    esrc[p] = ei[e];
}

// ================= aggregation: z = h[n] + sum_{src->n} h[src] =============
// 128-thread CTAs (nodes retire independently at D>=512), 4-wide body with
// index prefetch: next group's indices load while current group's gathers run.
template <int D>
__global__ void __launch_bounds__(128)
aggregate_kernel(const float* __restrict__ h, const int* __restrict__ off,
                 const int* __restrict__ cnt, const int* __restrict__ esrc,
                 __nv_bfloat162* __restrict__ hi, __nv_bfloat162* __restrict__ lo) {
    constexpr int TPN = D / 4;
    constexpr int NPB = 128 / TPN;
    const int node = blockIdx.x * NPB + threadIdx.x / TPN;
    if (node >= N_NODES) return;
    const int t = threadIdx.x % TPN;
    const float4* hp = (const float4*)h;

    float4 acc = hp[(size_t)node * TPN + t];
    const int s = off[node];
    const int e = s + cnt[node];
    int i = s;
    if (i + 4 <= e) {
        int p0 = esrc[i], p1 = esrc[i + 1], p2 = esrc[i + 2], p3 = esrc[i + 3];
#pragma unroll 1
        for (; i + 8 <= e; i += 4) {
            int n0 = esrc[i + 4], n1 = esrc[i + 5], n2 = esrc[i + 6], n3 = esrc[i + 7];
            float4 v0 = hp[(size_t)p0 * TPN + t];
            float4 v1 = hp[(size_t)p1 * TPN + t];
            float4 v2 = hp[(size_t)p2 * TPN + t];
            float4 v3 = hp[(size_t)p3 * TPN + t];
            acc.x += v0.x + v1.x + v2.x + v3.x;
            acc.y += v0.y + v1.y + v2.y + v3.y;
            acc.z += v0.z + v1.z + v2.z + v3.z;
            acc.w += v0.w + v1.w + v2.w + v3.w;
            p0 = n0; p1 = n1; p2 = n2; p3 = n3;
        }
        float4 v0 = hp[(size_t)p0 * TPN + t];
        float4 v1 = hp[(size_t)p1 * TPN + t];
        float4 v2 = hp[(size_t)p2 * TPN + t];
        float4 v3 = hp[(size_t)p3 * TPN + t];
        acc.x += v0.x + v1.x + v2.x + v3.x;
        acc.y += v0.y + v1.y + v2.y + v3.y;
        acc.z += v0.z + v1.z + v2.z + v3.z;
        acc.w += v0.w + v1.w + v2.w + v3.w;
        i += 4;
    }
    for (; i < e; i++) {
        float4 v = hp[(size_t)esrc[i] * TPN + t];
        acc.x += v.x; acc.y += v.y; acc.z += v.z; acc.w += v.w;
    }
    __nv_bfloat162 l0, l1;
    __nv_bfloat162 h0 = split_hi2(acc.x, acc.y, l0);
    __nv_bfloat162 h1 = split_hi2(acc.z, acc.w, l1);
    size_t o = (size_t)node * (D / 2) + t * 2;
    hi[o] = h0; hi[o + 1] = h1;
    lo[o] = l0; lo[o + 1] = l1;
}

// ---------------- activation hi/lo split (only for x) -----------------------
__global__ void asplit_kernel(const float4* __restrict__ A,
                              __nv_bfloat162* __restrict__ hi, __nv_bfloat162* __restrict__ lo, long n4) {
    long i = (long)blockIdx.x * 256 + threadIdx.x;
    if (i >= n4) return;
    float4 v = A[i];
    __nv_bfloat162 l0, l1;
    __nv_bfloat162 h0 = split_hi2(v.x, v.y, l0);
    __nv_bfloat162 h1 = split_hi2(v.z, v.w, l1);
    hi[2 * i] = h0; hi[2 * i + 1] = h1;
    lo[2 * i] = l0; lo[2 * i + 1] = l1;
}

// ---------------- batched weight transpose + hi/lo split --------------------
struct WSplitJob { const float* w; __nv_bfloat16* hi; __nv_bfloat16* lo; int K, DO, tileBase; };
struct WSplitParams { WSplitJob jobs[9]; };

__global__ void wsplit_all_kernel(WSplitParams p) {
    const int b = blockIdx.x;
    int j = 0;
#pragma unroll
    for (int i = 1; i < 9; i++)
        if (b >= p.jobs[i].tileBase) j = i;
    const float* W = p.jobs[j].w;
    __nv_bfloat16* hi = p.jobs[j].hi;
    __nv_bfloat16* lo = p.jobs[j].lo;
    const int K = p.jobs[j].K, DO = p.jobs[j].DO;
    const int t = b - p.jobs[j].tileBase;
    const int tilesX = DO / 32;
    const int bx = t % tilesX, by = t / tilesX;

    __shared__ float s[32][33];
    int tx = threadIdx.x, ty = threadIdx.y;
    int k = by * 32 + ty, n = bx * 32 + tx;
    s[ty][tx] = W[(size_t)k * DO + n];
    __syncthreads();
    int on = bx * 32 + ty, ok = by * 32 + tx;
    float x = s[tx][ty];
    __nv_bfloat16 h = __float2bfloat16(x);
    __nv_bfloat16 l = __float2bfloat16(x - __bfloat162float(h));
    hi[(size_t)on * K + ok] = h;
    lo[(size_t)on * K + ok] = l;
}

// ---------------- split-bf16 HMMA GEMM pieces, BM=128 BN=256 BK=32 -----------
#define ROWB 80
#define A_PLANE (128 * ROWB)
#define B_PLANE (256 * ROWB)
#define STAGEB (2 * A_PLANE + 2 * B_PLANE)  // 61440
#define NSTAGE 3
#define GEMM_SMEM (NSTAGE * STAGEB)         // 184320
#define GEMM_THREADS 512

__device__ __forceinline__ void mma_loop(
    uint32_t sb, int bm, int bn,
    const __nv_bfloat16* __restrict__ Ahi, const __nv_bfloat16* __restrict__ Alo,
    const __nv_bfloat16* __restrict__ Bhi, const __nv_bfloat16* __restrict__ Blo,
    int N, int K, float (&acc)[2][8][4]) {
    const int tid = threadIdx.x;
    const int lane = tid & 31;
    const int wid = tid >> 5;
    const int wm = wid & 3;
    const int wn = wid >> 2;
    const int NC = K >> 5;

    auto load_stage = [&](int chunk, int s) {
        const uint32_t base = sb + s * STAGEB;
        const int k0 = chunk << 5;
        {
            int row = tid >> 2, c = tid & 3;
            uint32_t off = (uint32_t)row * ROWB + (uint32_t)c * 16u;
            long arow = bm + row;
            bool ok = arow < N;
            size_t ao = (size_t)(ok ? arow : 0) * K + k0 + c * 8;
            cp16(base + off,           Ahi + ao, ok);
            cp16(base + A_PLANE + off, Alo + ao, ok);
        }
#pragma unroll
        for (int j = 0; j < 2; j++) {
            int p = tid + j * GEMM_THREADS;
            int row = p >> 2, c = p & 3;
            uint32_t off = (uint32_t)row * ROWB + (uint32_t)c * 16u;
            size_t bo = (size_t)(bn + row) * K + k0 + c * 8;
            cp16(base + 2 * A_PLANE + off,           Bhi + bo, true);
            cp16(base + 2 * A_PLANE + B_PLANE + off, Blo + bo, true);
        }
    };

    load_stage(0, 0);
    CP_COMMIT();
    if (NC > 1) load_stage(1, 1);
    CP_COMMIT();

    const int a_row = wm * 32 + (lane & 15);
    const int a_cc  = (lane >> 4);
    const int b_row = wn * 64 + ((lane >> 4) << 3) + (lane & 7);
    const int b_cc  = ((lane >> 3) & 1);

    for (int i = 0; i < NC; i++) {
        asm volatile("cp.async.wait_group 1;" ::: "memory");
        __syncthreads();
        const int pf = i + 2;
        if (pf < NC) load_stage(pf, pf % NSTAGE);
        CP_COMMIT();

        const uint32_t sA  = sb + (i % NSTAGE) * STAGEB;
        const uint32_t sAl = sA + A_PLANE;
        const uint32_t sB  = sA + 2 * A_PLANE;
        const uint32_t sBl = sB + B_PLANE;

#pragma unroll
        for (int ks = 0; ks < 2; ks++) {
            uint32_t ah[2][4], al[2][4];
#pragma unroll
            for (int t = 0; t < 2; t++) {
                uint32_t off = (uint32_t)(a_row + t * 16) * ROWB + (uint32_t)(a_cc + ks * 2) * 16u;
                LDSM4(ah[t][0], ah[t][1], ah[t][2], ah[t][3], sA + off);
                LDSM4(al[t][0], al[t][1], al[t][2], al[t][3], sAl + off);
            }
#pragma unroll
            for (int g = 0; g < 4; g++) {
                uint32_t bh[2][2], bl[2][2];
                uint32_t off = (uint32_t)(b_row + g * 16) * ROWB + (uint32_t)(b_cc + ks * 2) * 16u;
                LDSM4(bh[0][0], bh[0][1], bh[1][0], bh[1][1], sB + off);
                LDSM4(bl[0][0], bl[0][1], bl[1][0], bl[1][1], sBl + off);
#pragma unroll
                for (int t = 0; t < 2; t++)
#pragma unroll
                    for (int s2 = 0; s2 < 2; s2++)
                        MMA16816(acc[t][2 * g + s2], ah[t], bh[s2]);
#pragma unroll
                for (int t = 0; t < 2; t++)
#pragma unroll
                    for (int s2 = 0; s2 < 2; s2++)
                        MMA16816(acc[t][2 * g + s2], ah[t], bl[s2]);
#pragma unroll
                for (int t = 0; t < 2; t++)
#pragma unroll
                    for (int s2 = 0; s2 < 2; s2++)
                        MMA16816(acc[t][2 * g + s2], al[t], bh[s2]);
            }
        }
    }
}

// t = relu(A@Wt + bias) -> split bf16 planes
__global__ void __launch_bounds__(GEMM_THREADS, 1)
gemm1_kernel(const __nv_bfloat16* __restrict__ Ahi, const __nv_bfloat16* __restrict__ Alo,
             const __nv_bfloat16* __restrict__ Bhi, const __nv_bfloat16* __restrict__ Blo,
             const float* __restrict__ bias,
             __nv_bfloat162* __restrict__ Chi, __nv_bfloat162* __restrict__ Clo,
             int N, int K, int DO) {
    extern __shared__ char smem[];
    const int bm = blockIdx.x * 128, bn = blockIdx.y * 256;
    const int lane = threadIdx.x & 31;
    const int wid = threadIdx.x >> 5;
    const int wm = wid & 3, wn = wid >> 2;

    float acc[2][8][4];
#pragma unroll
    for (int t = 0; t < 2; t++)
#pragma unroll
        for (int n = 0; n < 8; n++)
#pragma unroll
            for (int q = 0; q < 4; q++) acc[t][n][q] = 0.f;

    mma_loop(smem_u32(smem), bm, bn, Ahi, Alo, Bhi, Blo, N, K, acc);

#pragma unroll
    for (int t = 0; t < 2; t++) {
        const int rbase = bm + wm * 32 + t * 16 + (lane >> 2);
#pragma unroll
        for (int half = 0; half < 2; half++) {
            const long row = rbase + half * 8;
            if (row < N) {
#pragma unroll
                for (int n = 0; n < 8; n++) {
                    const int cb = bn + wn * 64 + n * 8 + (lane & 3) * 2;
                    float2 b2 = *(const float2*)(bias + cb);
                    float vx = fmaxf(acc[t][n][half * 2 + 0] + b2.x, 0.f);
                    float vy = fmaxf(acc[t][n][half * 2 + 1] + b2.y, 0.f);
                    __nv_bfloat162 lo2;
                    __nv_bfloat162 hi2 = split_hi2(vx, vy, lo2);
                    size_t o = ((size_t)row * DO + cb) >> 1;
                    Chi[o] = hi2;
                    Clo[o] = lo2;
                }
            }
        }
    }
}

// fused: z = relu( relu(T@Wb + bb) + Resin@Wr + rb )
__global__ void __launch_bounds__(GEMM_THREADS, 1)
gemm2f_kernel(const __nv_bfloat16* __restrict__ Thi, const __nv_bfloat16* __restrict__ Tlo,
              const __nv_bfloat16* __restrict__ Wbhi, const __nv_bfloat16* __restrict__ Wblo,
              const float* __restrict__ bb,
              const __nv_bfloat16* __restrict__ Rhi, const __nv_bfloat16* __restrict__ Rlo,
              const __nv_bfloat16* __restrict__ Wrhi, const __nv_bfloat16* __restrict__ Wrlo,
              const float* __restrict__ rb,
              float* __restrict__ C, int N, int K1, int K2, int DO) {
    extern __shared__ char smem[];
    const int bm = blockIdx.x * 128, bn = blockIdx.y * 256;
    const int lane = threadIdx.x & 31;
    const int wid = threadIdx.x >> 5;
    const int wm = wid & 3, wn = wid >> 2;
    const uint32_t sb = smem_u32(smem);

    float acc[2][8][4];
#pragma unroll
    for (int t = 0; t < 2; t++)
#pragma unroll
        for (int n = 0; n < 8; n++)
#pragma unroll
            for (int q = 0; q < 4; q++) acc[t][n][q] = 0.f;

    mma_loop(sb, bm, bn, Thi, Tlo, Wbhi, Wblo, N, K1, acc);

#pragma unroll
    for (int n = 0; n < 8; n++) {
        const int cb = bn + wn * 64 + n * 8 + (lane & 3) * 2;
        float2 b2 = *(const float2*)(bb + cb);
        float2 r2 = *(const float2*)(rb + cb);
#pragma unroll
        for (int t = 0; t < 2; t++) {
            acc[t][n][0] = fmaxf(acc[t][n][0] + b2.x, 0.f) + r2.x;
            acc[t][n][1] = fmaxf(acc[t][n][1] + b2.y, 0.f) + r2.y;
            acc[t][n][2] = fmaxf(acc[t][n][2] + b2.x, 0.f) + r2.x;
            acc[t][n][3] = fmaxf(acc[t][n][3] + b2.y, 0.f) + r2.y;
        }
    }

    asm volatile("cp.async.wait_group 0;" ::: "memory");
    __syncthreads();

    mma_loop(sb, bm, bn, Rhi, Rlo, Wrhi, Wrlo, N, K2, acc);

#pragma unroll
    for (int t = 0; t < 2; t++) {
        const int rbase = bm + wm * 32 + t * 16 + (lane >> 2);
#pragma unroll
        for (int half = 0; half < 2; half++) {
            const long row = rbase + half * 8;
            if (row < N) {
#pragma unroll
                for (int n = 0; n < 8; n++) {
                    const int cb = bn + wn * 64 + n * 8 + (lane & 3) * 2;
                    float2 o;
                    o.x = fmaxf(acc[t][n][half * 2 + 0], 0.f);
                    o.y = fmaxf(acc[t][n][half * 2 + 1], 0.f);
                    *(float2*)(C + row * DO + cb) = o;
                }
            }
        }
    }
}

// ---------------- row LayerNorm: blockDim.x == D/4 exactly -------------------
__global__ void ln_kernel(const float* __restrict__ in, const float* __restrict__ gam,
                          const float* __restrict__ bet, float* __restrict__ out,
                          __nv_bfloat162* __restrict__ ohi, __nv_bfloat162* __restrict__ olo,
                          int D) {
    const int row = blockIdx.x;
    const int i = threadIdx.x;
    const float4* ip = (const float4*)(in + (size_t)row * D);
    float4 x = ip[i];
    float s  = x.x + x.y + x.z + x.w;
    float ss = x.x * x.x + x.y * x.y + x.z * x.z + x.w * x.w;
#pragma unroll
    for (int o = 16; o; o >>= 1) {
        s  += __shfl_xor_sync(0xffffffffu, s, o);
        ss += __shfl_xor_sync(0xffffffffu, ss, o);
    }
    __shared__ float rs[8], rss[8], stats[2];
    const int w = i >> 5, l = i & 31;
    const int nw = blockDim.x >> 5;
    if (l == 0) { rs[w] = s; rss[w] = ss; }
    __syncthreads();
    if (i < 32) {
        float a = (i < nw) ? rs[i]  : 0.f;
        float b = (i < nw) ? rss[i] : 0.f;
#pragma unroll
        for (int o = 4; o; o >>= 1) {
            a += __shfl_xor_sync(0xffffffffu, a, o);
            b += __shfl_xor_sync(0xffffffffu, b, o);
        }
        if (i == 0) {
            float mu  = a / (float)D;
            float var = b / (float)D - mu * mu;
            stats[0] = mu;
            stats[1] = rsqrtf(var + 1e-5f);
        }
    }
    __syncthreads();
    const float mu = stats[0], inv = stats[1];
    float4 g = ((const float4*)gam)[i];
    float4 b = ((const float4*)bet)[i];
    float4 o;
    o.x = (x.x - mu) * inv * g.x + b.x;
    o.y = (x.y - mu) * inv * g.y + b.y;
    o.z = (x.z - mu) * inv * g.z + b.z;
    o.w = (x.w - mu) * inv * g.w + b.w;
    ((float4*)(out + (size_t)row * D))[i] = o;
    if (ohi) {
        __nv_bfloat162 l0, l1;
        __nv_bfloat162 h0 = split_hi2(o.x, o.y, l0);
        __nv_bfloat162 h1 = split_hi2(o.z, o.w, l1);
        size_t base = (size_t)row * (D >> 1) + i * 2;
        ohi[base] = h0; ohi[base + 1] = h1;
        olo[base] = l0; olo[base + 1] = l1;
    }
}

// ---------------- host orchestration ----------------------------------------
extern "C" void kernel_launch(void* const* d_in, const int* in_sizes, int n_in,
                              void* d_out, int out_size) {
    const float* x   = (const float*)d_in[0];
    const int*   ei  = (const int*)d_in[1];
    const float* w1a = (const float*)d_in[2];
    const float* b1a = (const float*)d_in[3];
    const float* w1b = (const float*)d_in[4];
    const float* b1b = (const float*)d_in[5];
    const float* w2a = (const float*)d_in[6];
    const float* b2a = (const float*)d_in[7];
    const float* w2b = (const float*)d_in[8];
    const float* b2b = (const float*)d_in[9];
    const float* w3a = (const float*)d_in[10];
    const float* b3a = (const float*)d_in[11];
    const float* w3b = (const float*)d_in[12];
    const float* b3b = (const float*)d_in[13];
    const float* rp1w = (const float*)d_in[14];
    const float* rp1b = (const float*)d_in[15];
    const float* rp2w = (const float*)d_in[16];
    const float* rp2b = (const float*)d_in[17];
    const float* rp3w = (const float*)d_in[18];
    const float* rp3b = (const float*)d_in[19];
    const float* ln1g = (const float*)d_in[20];
    const float* ln1b = (const float*)d_in[21];
    const float* ln2g = (const float*)d_in[22];
    const float* ln2b = (const float*)d_in[23];
    const float* ln3g = (const float*)d_in[24];
    const float* ln3b = (const float*)d_in[25];
    float* out = (float*)d_out;

    float *z, *h;
    __nv_bfloat16 *a1hi, *a1lo, *a2hi, *a2lo, *a3hi, *a3lo, *whi, *wlo;
    int *csr_cnt, *csr_off, *csr_cur, *esrc, *bsum;
    cudaGetSymbolAddress((void**)&z, g_z);
    cudaGetSymbolAddress((void**)&h, g_h);
    cudaGetSymbolAddress((void**)&a1hi, g_a1hi);
    cudaGetSymbolAddress((void**)&a1lo, g_a1lo);
    cudaGetSymbolAddress((void**)&a2hi, g_a2hi);
    cudaGetSymbolAddress((void**)&a2lo, g_a2lo);
    cudaGetSymbolAddress((void**)&a3hi, g_a3hi);
    cudaGetSymbolAddress((void**)&a3lo, g_a3lo);
    cudaGetSymbolAddress((void**)&whi, g_whi);
    cudaGetSymbolAddress((void**)&wlo, g_wlo);
    cudaGetSymbolAddress((void**)&csr_cnt, g_cnt);
    cudaGetSymbolAddress((void**)&csr_off, g_off);
    cudaGetSymbolAddress((void**)&csr_cur, g_cur);
    cudaGetSymbolAddress((void**)&esrc, g_esrc);
    cudaGetSymbolAddress((void**)&bsum, g_bsum);

    cudaFuncSetAttribute(gemm1_kernel, cudaFuncAttributeMaxDynamicSharedMemorySize, GEMM_SMEM);
    cudaFuncSetAttribute(gemm2f_kernel, cudaFuncAttributeMaxDynamicSharedMemorySize, GEMM_SMEM);

    // ---- CSR build (once per call) ----
    const int NB = (N_NODES + 255) / 256;
    const int EB = (N_EDGES + 255) / 256;
    csr_zero<<<NB, 256>>>(csr_cnt, csr_cur);
    csr_hist<<<EB, 256>>>(ei, csr_cnt);
    csr_scan1<<<NB, 256>>>(csr_cnt, csr_off, bsum);
    csr_scan2<<<1, 256>>>(bsum, NB);
    csr_scan3<<<NB, 256>>>(csr_off, bsum);
    csr_fill<<<EB, 256>>>(ei, csr_off, csr_cur, esrc);

    // ---- weight split: one batched launch ----
    const size_t o_w1a = 0;
    const size_t o_w1b = o_w1a + 128 * 256;
    const size_t o_rp1 = o_w1b + 256 * 256;
    const size_t o_w2a = o_rp1 + 128 * 256;
    const size_t o_w2b = o_w2a + 256 * 512;
    const size_t o_rp2 = o_w2b + 512 * 512;
    const size_t o_w3a = o_rp2 + 256 * 512;
    const size_t o_w3b = o_w3a + 512 * 1024;
    const size_t o_rp3 = o_w3b + 1024 * 1024;

    {
        struct Src { const float* w; size_t off; int K, DO; };
        const Src srcs[9] = {
            {w1a, o_w1a, 128, 256},  {w1b, o_w1b, 256, 256},   {rp1w, o_rp1, 128, 256},
            {w2a, o_w2a, 256, 512},  {w2b, o_w2b, 512, 512},   {rp2w, o_rp2, 256, 512},
            {w3a, o_w3a, 512, 1024}, {w3b, o_w3b, 1024, 1024}, {rp3w, o_rp3, 512, 1024},
        };
        WSplitParams p;
        int tiles = 0;
        for (int i = 0; i < 9; i++) {
            p.jobs[i].w = srcs[i].w;
            p.jobs[i].hi = whi + srcs[i].off;
            p.jobs[i].lo = wlo + srcs[i].off;
            p.jobs[i].K = srcs[i].K;
            p.jobs[i].DO = srcs[i].DO;
            p.jobs[i].tileBase = tiles;
            tiles += (srcs[i].DO / 32) * (srcs[i].K / 32);
        }
        dim3 b(32, 32);
        wsplit_all_kernel<<<tiles, b>>>(p);
    }

    // residual input split for block 1 (x)
    {
        long n4 = (long)N_NODES * 128 / 4;
        asplit_kernel<<<(unsigned)((n4 + 255) / 256), 256>>>(
            (const float4*)x, (__nv_bfloat162*)a2hi, (__nv_bfloat162*)a2lo, n4);
    }

    const __nv_bfloat16* rw_hi[3] = {whi + o_rp1, whi + o_rp2, whi + o_rp3};
    const __nv_bfloat16* rw_lo[3] = {wlo + o_rp1, wlo + o_rp2, wlo + o_rp3};
    const float* rb[3] = {rp1b, rp2b, rp3b};
    const __nv_bfloat16* wa_hi[3] = {whi + o_w1a, whi + o_w2a, whi + o_w3a};
    const __nv_bfloat16* wa_lo[3] = {wlo + o_w1a, wlo + o_w2a, wlo + o_w3a};
    const float* ba[3] = {b1a, b2a, b3a};
    const __nv_bfloat16* wb_hi[3] = {whi + o_w1b, whi + o_w2b, whi + o_w3b};
    const __nv_bfloat16* wb_lo[3] = {wlo + o_w1b, wlo + o_w2b, wlo + o_w3b};
    const float* bb[3] = {b1b, b2b, b3b};
    const float* lg[3] = {ln1g, ln2g, ln3g};
    const float* lb[3] = {ln1b, ln2b, ln3b};
    const int din[3]  = {128, 256, 512};
    const int dout[3] = {256, 512, 1024};
    const float* blockIn[3] = {x, h, h};

    const int gx = (N_NODES + 127) / 128;

    for (int blk = 0; blk < 3; blk++) {
        const int d = din[blk], dO = dout[blk];

        // aggregation (memory-bound, high occupancy, 128-thread CTAs)
        if (blk == 0)
            aggregate_kernel<128><<<(N_NODES + 3) / 4, 128>>>(blockIn[blk], csr_off, csr_cnt, esrc,
                                                              (__nv_bfloat162*)a1hi, (__nv_bfloat162*)a1lo);
        else if (blk == 1)
            aggregate_kernel<256><<<(N_NODES + 1) / 2, 128>>>(blockIn[blk], csr_off, csr_cnt, esrc,
                                                              (__nv_bfloat162*)a1hi, (__nv_bfloat162*)a1lo);
        else
            aggregate_kernel<512><<<N_NODES, 128>>>(blockIn[blk], csr_off, csr_cnt, esrc,
                                                    (__nv_bfloat162*)a1hi, (__nv_bfloat162*)a1lo);

        // t = relu(agg@Wa+ba) -> split planes a3
        {
            dim3 grid(gx, dO / 256);
            gemm1_kernel<<<grid, GEMM_THREADS, GEMM_SMEM>>>(
                a1hi, a1lo, wa_hi[blk], wa_lo[blk], ba[blk],
                (__nv_bfloat162*)a3hi, (__nv_bfloat162*)a3lo, N_NODES, d, dO);
        }

        // z = relu( relu(t@Wb+bb) + resin@Wr + rb )   (fused residual GEMM)
        {
            dim3 grid(gx, dO / 256);
            gemm2f_kernel<<<grid, GEMM_THREADS, GEMM_SMEM>>>(
                a3hi, a3lo, wb_hi[blk], wb_lo[blk], bb[blk],
                a2hi, a2lo, rw_hi[blk], rw_lo[blk], rb[blk],
                z, N_NODES, dO, d, dO);
        }

        // LN (writes next block's residual-input split planes, except last)
        if (blk < 2)
            ln_kernel<<<N_NODES, dO / 4>>>(z, lg[blk], lb[blk], h,
                                           (__nv_bfloat162*)a2hi, (__nv_bfloat162*)a2lo, dO);
        else
            ln_kernel<<<N_NODES, dO / 4>>>(z, lg[blk], lb[blk], out, nullptr, nullptr, dO);
    }
}